// round 6
// baseline (speedup 1.0000x reference)
#include <cuda_runtime.h>
#include <math.h>

#define L_LAYERS 32
#define BEAM 8
#define KV2 2
#define HEADS 8
#define SEQ 1024
#define HDIM 64
#define VOCAB 50257
#define HIST 128
#define TOPK 8
#define CHUNKS 32
#define CHUNK_SZ 1664          // 13 * 128; 32*1664 = 53248 >= 50257
#define EPT 13                 // elements per thread in chunk_topk

// per-(l,b) slab: KV2*HEADS*SEQ*HDIM floats = 1,048,576 floats = 262,144 float4
#define SLAB_F4 262144
#define GRPS_PER_LAYER 256     // 262144 f4 / 1024 f4 per block

// output offsets (float32 elements, concatenated in reference return order)
#define OFF_KV   0LL
#define OFF_SAVE 268435456LL
#define OFF_PROB 268436488LL
#define OFF_TBI  268436496LL
#define OFF_MAX  268436504LL

// device-global scratch (no allocations allowed)
__device__ float g_part_m[BEAM * CHUNKS];
__device__ float g_part_s[BEAM * CHUNKS];
__device__ float g_part_val[BEAM * CHUNKS * TOPK];
__device__ int   g_part_idx[BEAM * CHUNKS * TOPK];
__device__ int   g_beam_index[BEAM];

__device__ __forceinline__ bool cand_gt(float av, int ai, float bv, int bi) {
    // strictly greater value wins; on exact tie, lower index wins (jax.lax.top_k order)
    return (av > bv) || (av == bv && ai < bi);
}

// ---------------------------------------------------------------------------
// Kernel 1: per-chunk softmax partials (m, s) + top-8, register-batched loads.
// grid = BEAM*CHUNKS = 256 blocks, 128 threads.
// ---------------------------------------------------------------------------
__global__ void __launch_bounds__(128) chunk_topk_kernel(const float* __restrict__ logits) {
    const int chunk = blockIdx.x & (CHUNKS - 1);
    const int r     = blockIdx.x >> 5;
    const int tid   = threadIdx.x;
    const int start = chunk * CHUNK_SZ;
    const float* row = logits + (long long)r * VOCAB;

    // batch all loads first: 13 independent predicated loads -> full MLP
    float v[EPT];
    int   vi[EPT];
#pragma unroll
    for (int j = 0; j < EPT; j++) {
        int i = start + tid + j * 128;
        bool ok = (i < VOCAB);
        v[j]  = ok ? row[i] : -INFINITY;
        vi[j] = ok ? i : 0x7fffffff;
    }

    // local max
    float m = v[0];
#pragma unroll
    for (int j = 1; j < EPT; j++) m = fmaxf(m, v[j]);

    // exp-sum against local max (no online rescale needed)
    float s = 0.0f;
    if (m > -INFINITY) {
#pragma unroll
        for (int j = 0; j < EPT; j++)
            if (v[j] > -INFINITY) s += __expf(v[j] - m);
    }

    // local sorted top-8
    float lv[TOPK];
    int   li[TOPK];
#pragma unroll
    for (int k = 0; k < TOPK; k++) { lv[k] = -INFINITY; li[k] = 0x7fffffff; }
#pragma unroll
    for (int j = 0; j < EPT; j++) {
        if (cand_gt(v[j], vi[j], lv[TOPK - 1], li[TOPK - 1])) {
            int k = TOPK - 1;
            while (k > 0 && cand_gt(v[j], vi[j], lv[k - 1], li[k - 1])) {
                lv[k] = lv[k - 1]; li[k] = li[k - 1]; k--;
            }
            lv[k] = v[j]; li[k] = vi[j];
        }
    }

    // block reduce (m, s)
    __shared__ float sm[128], ss[128];
    sm[tid] = m; ss[tid] = s;
    __syncthreads();
    for (int st = 64; st > 0; st >>= 1) {
        if (tid < st) {
            float m1 = sm[tid], s1 = ss[tid];
            float m2 = sm[tid + st], s2 = ss[tid + st];
            float M = fmaxf(m1, m2);
            float S = ((m1 > -INFINITY) ? s1 * __expf(m1 - M) : 0.0f)
                    + ((m2 > -INFINITY) ? s2 * __expf(m2 - M) : 0.0f);
            sm[tid] = M; ss[tid] = S;
        }
        __syncthreads();
    }

    // tree-merge 128 sorted 8-lists -> chunk top-8
    __shared__ float sv[128 * TOPK];
    __shared__ int   si[128 * TOPK];
#pragma unroll
    for (int k = 0; k < TOPK; k++) { sv[tid * TOPK + k] = lv[k]; si[tid * TOPK + k] = li[k]; }
    __syncthreads();

    for (int step = 1; step < 128; step <<= 1) {
        if ((tid & (2 * step - 1)) == 0) {
            float* A  = &sv[tid * TOPK];
            int*   Ai = &si[tid * TOPK];
            float* B  = &sv[(tid + step) * TOPK];
            int*   Bi = &si[(tid + step) * TOPK];
            float mv[TOPK]; int mi[TOPK];
            int pa = 0, pb = 0;
#pragma unroll
            for (int k = 0; k < TOPK; k++) {
                if (cand_gt(A[pa], Ai[pa], B[pb], Bi[pb])) { mv[k] = A[pa]; mi[k] = Ai[pa]; pa++; }
                else                                        { mv[k] = B[pb]; mi[k] = Bi[pb]; pb++; }
            }
#pragma unroll
            for (int k = 0; k < TOPK; k++) { A[k] = mv[k]; Ai[k] = mi[k]; }
        }
        __syncthreads();
    }

    if (tid == 0) {
        g_part_m[blockIdx.x] = sm[0];
        g_part_s[blockIdx.x] = ss[0];
    }
    if (tid < TOPK) {
        g_part_val[blockIdx.x * TOPK + tid] = sv[tid];
        g_part_idx[blockIdx.x * TOPK + tid] = si[tid];
    }
}

// ---------------------------------------------------------------------------
// Kernel 2: per-row merge (LSE + top-8), global beam top-8, small outputs.
// ---------------------------------------------------------------------------
__global__ void select_kernel(const int* __restrict__ save_id,
                              const float* __restrict__ prev_prob,
                              float* __restrict__ out) {
    __shared__ float cv[BEAM * TOPK];
    __shared__ int   ci[BEAM * TOPK];
    __shared__ int   s_beam[BEAM];
    __shared__ int   s_tbi[BEAM];
    __shared__ float s_prob[BEAM];

    const int tid = threadIdx.x;

    if (tid < BEAM) {
        const int r = tid;
        float M = -INFINITY;
        for (int c = 0; c < CHUNKS; c++) M = fmaxf(M, g_part_m[r * CHUNKS + c]);
        float S = 0.0f;
        for (int c = 0; c < CHUNKS; c++) {
            float pm = g_part_m[r * CHUNKS + c];
            if (pm > -INFINITY) S += g_part_s[r * CHUNKS + c] * __expf(pm - M);
        }
        const float lse = M + logf(S);

        const float* pv = &g_part_val[r * CHUNKS * TOPK];
        const int*   pi = &g_part_idx[r * CHUNKS * TOPK];
        int chosen[TOPK];
        for (int k = 0; k < TOPK; k++) {
            int best = -1;
            float bv = -INFINITY; int bidx = 0x7fffffff;
            for (int i = 0; i < CHUNKS * TOPK; i++) {
                bool skip = false;
                for (int p = 0; p < k; p++) if (chosen[p] == i) { skip = true; break; }
                if (skip) continue;
                if (best < 0 || cand_gt(pv[i], pi[i], bv, bidx)) {
                    best = i; bv = pv[i]; bidx = pi[i];
                }
            }
            chosen[k] = best;
            cv[r * TOPK + k] = bv - lse + prev_prob[r];
            ci[r * TOPK + k] = bidx;
        }
    }
    __syncthreads();

    if (tid == 0) {
        bool used[BEAM * TOPK];
        for (int i = 0; i < BEAM * TOPK; i++) used[i] = false;
        for (int b = 0; b < BEAM; b++) {
            int best = -1;
            for (int i = 0; i < BEAM * TOPK; i++) {
                if (used[i]) continue;
                if (best < 0 || cv[i] > cv[best]) best = i;  // strict > keeps lower flat index
            }
            used[best] = true;
            s_beam[b] = best >> 3;
            s_tbi[b]  = ci[best];
            s_prob[b] = cv[best];
            g_beam_index[b] = best >> 3;
        }
    }
    __syncthreads();

    for (int i = tid; i < BEAM * (HIST + 1); i += blockDim.x) {
        int b = i / (HIST + 1);
        int c = i % (HIST + 1);
        int val = (c < HIST) ? save_id[s_beam[b] * HIST + c] : s_tbi[b];
        out[OFF_SAVE + i] = (float)val;
    }
    if (tid < BEAM) {
        out[OFF_PROB + tid] = s_prob[tid];
        out[OFF_TBI + tid]  = (float)s_tbi[tid];
    }
    if (tid == 0) out[OFF_MAX] = (float)s_tbi[0];
}

// ---------------------------------------------------------------------------
// Kernel 3: kv_cache gather with STRUCTURAL read dedupe.
// One block = one (layer, 16KB offset chunk), serving ALL 8 destination beams.
// Duplicate source beams re-read the same lines from this SM's L1 (resident:
// 16KB << 228KB), so DRAM sees each unique source chunk exactly once.
// Writes use streaming (.cs) stores so they don't evict the read lines.
// grid = 32 layers * 256 chunks = 8192 blocks, 256 threads.
// ---------------------------------------------------------------------------
__global__ void __launch_bounds__(256) gather_kernel(const float4* __restrict__ kv,
                                                     float4* __restrict__ out) {
    __shared__ int bi[BEAM];
    if (threadIdx.x < BEAM) bi[threadIdx.x] = g_beam_index[threadIdx.x];
    __syncthreads();

    const int grp = blockIdx.x & (GRPS_PER_LAYER - 1);
    const int l   = blockIdx.x >> 8;
    const int off = grp * 1024 + threadIdx.x;
    const long long lbase = (long long)l * BEAM * SLAB_F4;

#pragma unroll
    for (int b = 0; b < BEAM; b++) {
        const long long src = lbase + (long long)bi[b] * SLAB_F4 + off;
        const long long dst = lbase + (long long)b    * SLAB_F4 + off;
#pragma unroll
        for (int i = 0; i < 4; i++) {
            float4 v = kv[src + i * 256];        // default policy -> L1-cached
            __stcs(&out[dst + i * 256], v);      // streaming store
        }
    }
}

// ---------------------------------------------------------------------------
extern "C" void kernel_launch(void* const* d_in, const int* in_sizes, int n_in,
                              void* d_out, int out_size) {
    const float* kv_cache  = (const float*)d_in[0];
    const float* logits    = (const float*)d_in[1];
    const int*   save_id   = (const int*)d_in[2];
    const float* prev_prob = (const float*)d_in[3];
    float* out = (float*)d_out;

    chunk_topk_kernel<<<BEAM * CHUNKS, 128>>>(logits);
    select_kernel<<<1, 256>>>(save_id, prev_prob, out);
    gather_kernel<<<L_LAYERS * GRPS_PER_LAYER, 256>>>(
        (const float4*)kv_cache, (float4*)(out + OFF_KV));
}

// round 8
// speedup vs baseline: 1.4214x; 1.4214x over previous
#include <cuda_runtime.h>
#include <math.h>

#define L_LAYERS 32
#define BEAM 8
#define KV2 2
#define HEADS 8
#define SEQ 1024
#define HDIM 64
#define VOCAB 50257
#define HIST 128
#define TOPK 8
#define CHUNKS 32
#define CHUNK_SZ 1571          // 32*1571 = 50272 >= 50257

// per-(l,b) slab: KV2*HEADS*SEQ*HDIM floats = 1,048,576 floats = 262,144 float4
#define SLAB_F4 262144
#define GRPS_PER_LAYER 256     // 262144 f4 / 1024 f4 per block
#define CHUNK_GLOBAL (L_LAYERS * GRPS_PER_LAYER)   // 8192

// output offsets (float32 elements, concatenated in reference return order)
#define OFF_KV   0LL
#define OFF_SAVE 268435456LL
#define OFF_PROB 268436488LL
#define OFF_TBI  268436496LL
#define OFF_MAX  268436504LL

// device-global scratch (no allocations allowed)
__device__ float g_part_m[BEAM * CHUNKS];
__device__ float g_part_s[BEAM * CHUNKS];
__device__ float g_part_val[BEAM * CHUNKS * TOPK];
__device__ int   g_part_idx[BEAM * CHUNKS * TOPK];
__device__ int   g_beam_index[BEAM];

__device__ __forceinline__ bool cand_gt(float av, int ai, float bv, int bi) {
    // strictly greater value wins; on exact tie, lower index wins (jax.lax.top_k order)
    return (av > bv) || (av == bv && ai < bi);
}

// ---------------------------------------------------------------------------
// Kernel 1: per-chunk online softmax (m, s) + top-8. (round-2 version, 26.8us)
// grid = BEAM*CHUNKS = 256 blocks, 128 threads.
// ---------------------------------------------------------------------------
__global__ void __launch_bounds__(128) chunk_topk_kernel(const float* __restrict__ logits) {
    const int chunk = blockIdx.x & (CHUNKS - 1);
    const int r     = blockIdx.x >> 5;
    const int tid   = threadIdx.x;
    const int start = chunk * CHUNK_SZ;
    const int end   = min(start + CHUNK_SZ, VOCAB);
    const float* row = logits + (long long)r * VOCAB;

    float m = -INFINITY, s = 0.0f;
    float lv[TOPK];
    int   li[TOPK];
#pragma unroll
    for (int j = 0; j < TOPK; j++) { lv[j] = -INFINITY; li[j] = 0x7fffffff; }

    for (int i = start + tid; i < end; i += 128) {
        float v = row[i];
        if (v > m) { s = s * __expf(m - v) + 1.0f; m = v; }
        else       { s += __expf(v - m); }
        if (cand_gt(v, i, lv[TOPK - 1], li[TOPK - 1])) {
            int j = TOPK - 1;
            while (j > 0 && cand_gt(v, i, lv[j - 1], li[j - 1])) {
                lv[j] = lv[j - 1]; li[j] = li[j - 1]; j--;
            }
            lv[j] = v; li[j] = i;
        }
    }

    __shared__ float sm[128], ss[128];
    sm[tid] = m; ss[tid] = s;
    __syncthreads();
    for (int st = 64; st > 0; st >>= 1) {
        if (tid < st) {
            float m1 = sm[tid], s1 = ss[tid];
            float m2 = sm[tid + st], s2 = ss[tid + st];
            float M = fmaxf(m1, m2);
            float S = ((m1 > -INFINITY) ? s1 * __expf(m1 - M) : 0.0f)
                    + ((m2 > -INFINITY) ? s2 * __expf(m2 - M) : 0.0f);
            sm[tid] = M; ss[tid] = S;
        }
        __syncthreads();
    }

    __shared__ float sv[128 * TOPK];
    __shared__ int   si[128 * TOPK];
#pragma unroll
    for (int j = 0; j < TOPK; j++) { sv[tid * TOPK + j] = lv[j]; si[tid * TOPK + j] = li[j]; }
    __syncthreads();

    for (int step = 1; step < 128; step <<= 1) {
        if ((tid & (2 * step - 1)) == 0) {
            float* A  = &sv[tid * TOPK];
            int*   Ai = &si[tid * TOPK];
            float* B  = &sv[(tid + step) * TOPK];
            int*   Bi = &si[(tid + step) * TOPK];
            float mv[TOPK]; int mi[TOPK];
            int pa = 0, pb = 0;
#pragma unroll
            for (int j = 0; j < TOPK; j++) {
                if (cand_gt(A[pa], Ai[pa], B[pb], Bi[pb])) { mv[j] = A[pa]; mi[j] = Ai[pa]; pa++; }
                else                                        { mv[j] = B[pb]; mi[j] = Bi[pb]; pb++; }
            }
#pragma unroll
            for (int j = 0; j < TOPK; j++) { A[j] = mv[j]; Ai[j] = mi[j]; }
        }
        __syncthreads();
    }

    if (tid == 0) {
        g_part_m[blockIdx.x] = sm[0];
        g_part_s[blockIdx.x] = ss[0];
    }
    if (tid < TOPK) {
        g_part_val[blockIdx.x * TOPK + tid] = sv[tid];
        g_part_idx[blockIdx.x * TOPK + tid] = si[tid];
    }
}

// ---------------------------------------------------------------------------
// Kernel 2: per-row merge (LSE + top-8), global beam top-8, small outputs.
// ---------------------------------------------------------------------------
__global__ void select_kernel(const int* __restrict__ save_id,
                              const float* __restrict__ prev_prob,
                              float* __restrict__ out) {
    __shared__ float cv[BEAM * TOPK];
    __shared__ int   ci[BEAM * TOPK];
    __shared__ int   s_beam[BEAM];
    __shared__ int   s_tbi[BEAM];
    __shared__ float s_prob[BEAM];

    const int tid = threadIdx.x;

    if (tid < BEAM) {
        const int r = tid;
        float M = -INFINITY;
        for (int c = 0; c < CHUNKS; c++) M = fmaxf(M, g_part_m[r * CHUNKS + c]);
        float S = 0.0f;
        for (int c = 0; c < CHUNKS; c++) {
            float pm = g_part_m[r * CHUNKS + c];
            if (pm > -INFINITY) S += g_part_s[r * CHUNKS + c] * __expf(pm - M);
        }
        const float lse = M + logf(S);

        const float* pv = &g_part_val[r * CHUNKS * TOPK];
        const int*   pi = &g_part_idx[r * CHUNKS * TOPK];
        int chosen[TOPK];
        for (int k = 0; k < TOPK; k++) {
            int best = -1;
            float bv = -INFINITY; int bidx = 0x7fffffff;
            for (int i = 0; i < CHUNKS * TOPK; i++) {
                bool skip = false;
                for (int p = 0; p < k; p++) if (chosen[p] == i) { skip = true; break; }
                if (skip) continue;
                if (best < 0 || cand_gt(pv[i], pi[i], bv, bidx)) {
                    best = i; bv = pv[i]; bidx = pi[i];
                }
            }
            chosen[k] = best;
            cv[r * TOPK + k] = bv - lse + prev_prob[r];
            ci[r * TOPK + k] = bidx;
        }
    }
    __syncthreads();

    if (tid == 0) {
        bool used[BEAM * TOPK];
        for (int i = 0; i < BEAM * TOPK; i++) used[i] = false;
        for (int b = 0; b < BEAM; b++) {
            int best = -1;
            for (int i = 0; i < BEAM * TOPK; i++) {
                if (used[i]) continue;
                if (best < 0 || cv[i] > cv[best]) best = i;
            }
            used[best] = true;
            s_beam[b] = best >> 3;
            s_tbi[b]  = ci[best];
            s_prob[b] = cv[best];
            g_beam_index[b] = best >> 3;
        }
    }
    __syncthreads();

    for (int i = tid; i < BEAM * (HIST + 1); i += blockDim.x) {
        int b = i / (HIST + 1);
        int c = i % (HIST + 1);
        int val = (c < HIST) ? save_id[s_beam[b] * HIST + c] : s_tbi[b];
        out[OFF_SAVE + i] = (float)val;
    }
    if (tid < BEAM) {
        out[OFF_PROB + tid] = s_prob[tid];
        out[OFF_TBI + tid]  = (float)s_tbi[tid];
    }
    if (tid == 0) out[OFF_MAX] = (float)s_tbi[0];
}

// ---------------------------------------------------------------------------
// Kernel 3: kv_cache gather, round-2 bandwidth structure with BEAM-INNERMOST
// block ordering. blockIdx = chunk_global * 8 + beam: the 8 blocks that read
// (potentially duplicated) source chunks are ADJACENT, so they run in the same
// wave on nearby SMs and duplicate-source reads hit L2 deterministically.
// Each block copies one 16KB chunk (1024 float4) for one destination beam.
// grid = 8192 * 8 = 65536 blocks, 256 threads, 4 independent float4 per thread.
// ---------------------------------------------------------------------------
__global__ void __launch_bounds__(256) gather_kernel(const float4* __restrict__ kv,
                                                     float4* __restrict__ out) {
    __shared__ int bi[BEAM];
    if (threadIdx.x < BEAM) bi[threadIdx.x] = g_beam_index[threadIdx.x];
    __syncthreads();

    const int b            = blockIdx.x & 7;          // beam innermost
    const int chunk_global = blockIdx.x >> 3;         // 0..8191
    const int grp          = chunk_global & (GRPS_PER_LAYER - 1);
    const int l            = chunk_global >> 8;

    const long long lbase = (long long)l * BEAM * SLAB_F4;
    const int off = grp * 1024 + threadIdx.x;

    const long long src = lbase + (long long)bi[b] * SLAB_F4 + off;
    const long long dst = lbase + (long long)b    * SLAB_F4 + off;

    // 4 independent loads batched, then 4 stores (preserve MLP)
    float4 v0 = kv[src];
    float4 v1 = kv[src + 256];
    float4 v2 = kv[src + 512];
    float4 v3 = kv[src + 768];
    out[dst]       = v0;
    out[dst + 256] = v1;
    out[dst + 512] = v2;
    out[dst + 768] = v3;
}

// ---------------------------------------------------------------------------
extern "C" void kernel_launch(void* const* d_in, const int* in_sizes, int n_in,
                              void* d_out, int out_size) {
    const float* kv_cache  = (const float*)d_in[0];
    const float* logits    = (const float*)d_in[1];
    const int*   save_id   = (const int*)d_in[2];
    const float* prev_prob = (const float*)d_in[3];
    float* out = (float*)d_out;

    chunk_topk_kernel<<<BEAM * CHUNKS, 128>>>(logits);
    select_kernel<<<1, 256>>>(save_id, prev_prob, out);
    gather_kernel<<<CHUNK_GLOBAL * BEAM, 256>>>(
        (const float4*)kv_cache, (float4*)(out + OFF_KV));
}